// round 11
// baseline (speedup 1.0000x reference)
#include <cuda_runtime.h>
#include <cuda_bf16.h>
#include <cstdint>

#define Bb 64
#define Vv 64
#define Tt 256
#define Ff 64
#define NEG_SLOPE 0.01f

// Transposed X: XT[t][b][w] = X[b][w][t] (makes fused-kernel X loads coalesced)
__device__ float g_XT[(size_t)Tt * Bb * Vv];     // 4 MB

__device__ __forceinline__ float fast_sigmoid(float x) {
    // sigmoid(x) = 0.5 + 0.5*tanh(0.5*x): single MUFU.TANH instead of EX2+RCP.
    float th;
    asm("tanh.approx.f32 %0, %1;" : "=f"(th) : "f"(0.5f * x));
    return fmaf(0.5f, th, 0.5f);
}

// ---------------------------------------------------------------------------
// X transpose (only remaining prep; hidden under fused's sigmoid phase via
// PDL). 32x32 smem tile, both sides coalesced.
// ---------------------------------------------------------------------------
__global__ __launch_bounds__(256) void x_transpose(const float* __restrict__ X) {
    const int t0 = (blockIdx.x & 7) * 32;        // 0..224
    const int b  = (blockIdx.x >> 3) & 63;       // 0..63
    const int w0 = (blockIdx.x >> 9) * 32;       // 0 or 32

    __shared__ float sm[32][33];

    const int tid = threadIdx.x;
    const int j  = tid & 31;
    const int i0 = tid >> 5;                     // 0..7

#pragma unroll
    for (int k = 0; k < 4; k++) {
        int i = i0 + k * 8;                      // w offset on read
        sm[i][j] = X[((size_t)b * Vv + (w0 + i)) * Tt + (t0 + j)];
    }
    __syncthreads();
#pragma unroll
    for (int k = 0; k < 4; k++) {
        int i = i0 + k * 8;                      // t offset on write
        g_XT[(size_t)(t0 + i) * (Bb * Vv) + (size_t)b * Vv + (w0 + j)] = sm[j][i];
    }
}

// ---------------------------------------------------------------------------
// Fused sigmoid + GEMM + expand. Block = (t, v-group of 8): owns adj rows
// v0..v0+7 -> sigmoid computed in-kernel with ZERO redundancy (adj_prep
// launch and its 8 MB DRAM round trip deleted). Reads full XT[t] tile
// (16 KB coalesced, L2-shared by the 8 blocks of t). Phase A (sigmoid, W)
// is independent of XT -> runs under x_transpose via PDL; griddepsync
// before touching g_XT.
// ---------------------------------------------------------------------------
__global__ __launch_bounds__(256) void fused_kernel(const float* __restrict__ A,
                                                    const float* __restrict__ W,
                                                    float* __restrict__ out) {
    const int t  = blockIdx.x;
    const int v0 = blockIdx.y << 3;    // 0,8,...,56

    __shared__ float sAdj[8 * Vv];     // 2 KB   [vloc][w]
    __shared__ float sXT[Bb * Vv];     // 16 KB  [b][w]
    __shared__ float sH[8][Bb];        // 2 KB   [vloc][b]

    const int tid = threadIdx.x;

    // ---- Phase A (independent of prep): W preselect + adj sigmoid ----
    float4 w4 = reinterpret_cast<const float4*>(W)[tid & 15];
    float4 wp, wn;
    wp.x = (w4.x >= 0.f) ? w4.x : NEG_SLOPE * w4.x;
    wp.y = (w4.y >= 0.f) ? w4.y : NEG_SLOPE * w4.y;
    wp.z = (w4.z >= 0.f) ? w4.z : NEG_SLOPE * w4.z;
    wp.w = (w4.w >= 0.f) ? w4.w : NEG_SLOPE * w4.w;
    wn.x = (w4.x >= 0.f) ? NEG_SLOPE * w4.x : w4.x;
    wn.y = (w4.y >= 0.f) ? NEG_SLOPE * w4.y : w4.y;
    wn.z = (w4.z >= 0.f) ? NEG_SLOPE * w4.z : w4.z;
    wn.w = (w4.w >= 0.f) ? NEG_SLOPE * w4.w : w4.w;

    if (tid < 128) {                   // 8 rows x 16 float4
        int vloc = tid >> 4, wq = tid & 15;
        int v = v0 + vloc;
        float4 a = reinterpret_cast<const float4*>(A)[(size_t)t * 1024 + (size_t)v * 16 + wq];
        float4 r;
        r.x = (v == 4 * wq + 0) ? 1.0f : fast_sigmoid(a.x);
        r.y = (v == 4 * wq + 1) ? 1.0f : fast_sigmoid(a.y);
        r.z = (v == 4 * wq + 2) ? 1.0f : fast_sigmoid(a.z);
        r.w = (v == 4 * wq + 3) ? 1.0f : fast_sigmoid(a.w);
        reinterpret_cast<float4*>(sAdj)[tid] = r;
    }

    // ---- Wait for x_transpose grid (PDL) ----
    cudaGridDependencySynchronize();

    // ---- Phase B: load XT[t] (16 KB, fully coalesced) ----
    {
        const float4* src = reinterpret_cast<const float4*>(g_XT) + (size_t)t * 1024;
        float4* dst = reinterpret_cast<float4*>(sXT);
#pragma unroll
        for (int k = 0; k < 4; k++) dst[tid + k * 256] = src[tid + k * 256];
    }
    __syncthreads();

    // ---- Phase C: GEMM. thread (b = tid>>3 (0..31), vloc = tid&7) does
    //      h[vloc][b] and h[vloc][b+32]. ----
    {
        const int b    = tid >> 3;
        const int vloc = tid & 7;
        const float4* arow = reinterpret_cast<const float4*>(sAdj) + vloc * 16;
        const float4* x0q  = reinterpret_cast<const float4*>(sXT) + b * 16;
        const float4* x1q  = reinterpret_cast<const float4*>(sXT) + (b + 32) * 16;
        float a0 = 0.f, a1 = 0.f;
#pragma unroll
        for (int wq = 0; wq < 16; wq++) {
            float4 s  = arow[wq];
            float4 x0 = x0q[wq];
            float4 x1 = x1q[wq];
            a0 = fmaf(s.x, x0.x, fmaf(s.y, x0.y, fmaf(s.z, x0.z, fmaf(s.w, x0.w, a0))));
            a1 = fmaf(s.x, x1.x, fmaf(s.y, x1.y, fmaf(s.z, x1.z, fmaf(s.w, x1.w, a1))));
        }
        sH[vloc][b] = a0;
        sH[vloc][b + 32] = a1;
    }
    __syncthreads();

    // ---- Phase D: stores. Per b: 2 KB contiguous segment (8v x 64f). ----
    float4* obase = reinterpret_cast<float4*>(out) + (size_t)t * 1024 + (size_t)v0 * 16;
    const int q  = tid & 127;          // v-f index within segment: v = q>>4, f4 = q&15
    const int bh = tid >> 7;           // 0 or 1
    const float* hcol = &sH[q >> 4][0];
#pragma unroll
    for (int it = 0; it < 32; it++) {
        int bb = it * 2 + bh;
        float h = hcol[bb];
        bool pos = (h >= 0.f);
        float4 r;
        r.x = h * (pos ? wp.x : wn.x);
        r.y = h * (pos ? wp.y : wn.y);
        r.z = h * (pos ? wp.z : wn.z);
        r.w = h * (pos ? wp.w : wn.w);
        __stcs(obase + (size_t)bb * (Tt * 1024) + q, r);
    }
}

extern "C" void kernel_launch(void* const* d_in, const int* in_sizes, int n_in,
                              void* d_out, int out_size) {
    const float* X = (const float*)d_in[0];   // [B, V, T]
    const float* A = (const float*)d_in[1];   // [T, V, V]
    const float* W = (const float*)d_in[2];   // [F, 1]
    float* out = (float*)d_out;               // [B, T, V*F]

    x_transpose<<<1024, 256>>>(X);

    // Fused kernel launched with Programmatic Stream Serialization: its
    // Phase A (sigmoid of A + W preselect) overlaps x_transpose; the
    // cudaGridDependencySynchronize() inside gates the g_XT reads.
    cudaLaunchConfig_t cfg = {};
    cfg.gridDim  = dim3(Tt, Vv / 8);
    cfg.blockDim = dim3(256);
    cfg.dynamicSmemBytes = 0;
    cfg.stream = 0;
    cudaLaunchAttribute attr[1];
    attr[0].id = cudaLaunchAttributeProgrammaticStreamSerialization;
    attr[0].val.programmaticStreamSerializationAllowed = 1;
    cfg.attrs = attr;
    cfg.numAttrs = 1;
    cudaLaunchKernelEx(&cfg, fused_kernel, A, W, (float*)d_out);
}

// round 13
// speedup vs baseline: 1.2807x; 1.2807x over previous
#include <cuda_runtime.h>
#include <cuda_bf16.h>
#include <cstdint>

#define Bb 64
#define Vv 64
#define Tt 256
#define Ff 64
#define NEG_SLOPE 0.01f

// Precomputed transposed adjacency: adjT[t][w][v] = sigmoid(A[t][v][w]) off-diag, 1 on diag.
__device__ float g_adjT[(size_t)Tt * Vv * Vv];   // 4 MB

__device__ __forceinline__ float fast_sigmoid(float x) {
    // sigmoid(x) = 0.5 + 0.5*tanh(0.5*x): single MUFU.TANH instead of EX2+RCP.
    float th;
    asm("tanh.approx.f32 %0, %1;" : "=f"(th) : "f"(0.5f * x));
    return fmaf(0.5f, th, 0.5f);
}

// ---------------------------------------------------------------------------
// Prep (R8): sigmoid once per element via MUFU.TANH; 512 blocks; 32x64 smem
// tile; reads and transposed writes both 128B-coalesced. ~1.5us, and hidden
// under the fused kernel's X-gather prologue via PDL.
// ---------------------------------------------------------------------------
__global__ __launch_bounds__(256) void adj_prep(const float* __restrict__ A) {
    const int t  = blockIdx.x;
    const int v0 = blockIdx.y * 32;    // 0 or 32

    __shared__ float sm[32][Vv + 1];   // [vloc][w]

    const int tid = threadIdx.x;
    const float4* A4 = reinterpret_cast<const float4*>(A) + (size_t)t * 1024 + v0 * 16;

#pragma unroll
    for (int k = 0; k < 2; k++) {
        int idx4 = tid + k * 256;          // vloc*16 + wq
        int vloc = idx4 >> 4, wq = idx4 & 15;
        int v = v0 + vloc;
        float4 a = A4[idx4];
        float av[4] = {a.x, a.y, a.z, a.w};
#pragma unroll
        for (int i = 0; i < 4; i++) {
            int w = wq * 4 + i;
            sm[vloc][w] = (v == w) ? 1.0f : fast_sigmoid(av[i]);
        }
    }
    __syncthreads();

    float* dst = g_adjT + (size_t)t * 4096 + v0;
#pragma unroll
    for (int k = 0; k < 8; k++) {
        int idx = tid + k * 256;           // w*32 + vloc
        int w = idx >> 5, vloc = idx & 31;
        dst[w * 64 + vloc] = sm[vloc][w];
    }
}

// ---------------------------------------------------------------------------
// Fused GEMM + expand — exact R4 winner shape (2048 blocks, 256 thr, 20 KB
// smem, 8/SM), reordered for PDL: the X gather + W preselect (independent of
// g_adjT) run BEFORE cudaGridDependencySynchronize(), covering adj_prep;
// only the adjT staging waits.
// ---------------------------------------------------------------------------
__global__ __launch_bounds__(256) void fused_kernel(const float* __restrict__ X,
                                                    const float* __restrict__ W,
                                                    float* __restrict__ out) {
    const int t  = blockIdx.x;
    const int b0 = blockIdx.y << 3;    // 0,8,...,56

    __shared__ float sAT[Vv * Vv];     // 16 KB, [w][v]
    __shared__ float sX[8][Vv];        // 2 KB
    __shared__ float sH[8][Vv];        // 2 KB

    const int tid = threadIdx.x;

    // ---- Pre-sync phase: X gather (slow, scattered -> good PDL cover) ----
#pragma unroll
    for (int k = 0; k < 2; k++) {
        int idx = tid + k * 256;           // bb*64 + w
        int bb = idx >> 6, w = idx & 63;
        sX[bb][w] = __ldg(&X[((size_t)(b0 + bb) * Vv + w) * Tt + t]);
    }

    // W preselect: leaky(h*w) = h * (h>=0 ? wp : wn)
    float4 w4 = reinterpret_cast<const float4*>(W)[tid & 15];
    float4 wp, wn;
    wp.x = (w4.x >= 0.f) ? w4.x : NEG_SLOPE * w4.x;
    wp.y = (w4.y >= 0.f) ? w4.y : NEG_SLOPE * w4.y;
    wp.z = (w4.z >= 0.f) ? w4.z : NEG_SLOPE * w4.z;
    wp.w = (w4.w >= 0.f) ? w4.w : NEG_SLOPE * w4.w;
    wn.x = (w4.x >= 0.f) ? NEG_SLOPE * w4.x : w4.x;
    wn.y = (w4.y >= 0.f) ? NEG_SLOPE * w4.y : w4.y;
    wn.z = (w4.z >= 0.f) ? NEG_SLOPE * w4.z : w4.z;
    wn.w = (w4.w >= 0.f) ? NEG_SLOPE * w4.w : w4.w;

    // ---- Wait for adj_prep grid (PDL), then stage adjT[t] ----
    cudaGridDependencySynchronize();
    {
        const float4* src = reinterpret_cast<const float4*>(g_adjT) + (size_t)t * 1024;
        float4* dst = reinterpret_cast<float4*>(sAT);
#pragma unroll
        for (int k = 0; k < 4; k++) dst[tid + k * 256] = src[tid + k * 256];
    }
    __syncthreads();

    // Mini-GEMM: thread (v = tid&63, g = tid>>6) computes h[g][v], h[g+4][v].
    {
        const int v = tid & 63;
        const int g = tid >> 6;
        const float4* x0q = reinterpret_cast<const float4*>(&sX[g][0]);
        const float4* x1q = reinterpret_cast<const float4*>(&sX[g + 4][0]);
        float a0 = 0.f, a1 = 0.f;
#pragma unroll
        for (int wq = 0; wq < 16; wq++) {
            float4 x0 = x0q[wq];
            float4 x1 = x1q[wq];
            float s0 = sAT[(4 * wq + 0) * 64 + v];
            float s1 = sAT[(4 * wq + 1) * 64 + v];
            float s2 = sAT[(4 * wq + 2) * 64 + v];
            float s3 = sAT[(4 * wq + 3) * 64 + v];
            a0 = fmaf(s0, x0.x, fmaf(s1, x0.y, fmaf(s2, x0.z, fmaf(s3, x0.w, a0))));
            a1 = fmaf(s0, x1.x, fmaf(s1, x1.y, fmaf(s2, x1.z, fmaf(s3, x1.w, a1))));
        }
        sH[g][v] = a0;
        sH[g + 4][v] = a1;
    }
    __syncthreads();

    // Store phase: 8 x 16 KB tiles of leaky(h*W), coalesced float4 streaming stores.
    float4* obase = reinterpret_cast<float4*>(out);
#pragma unroll
    for (int bb = 0; bb < 8; bb++) {
        float4* o = obase + ((size_t)(b0 + bb) * Tt + t) * 1024;
        const float* hrow = sH[bb];
#pragma unroll
        for (int k = 0; k < 4; k++) {
            int q = tid + k * 256;            // q&15 == tid&15, q>>4 = v
            float h = hrow[q >> 4];
            bool pos = (h >= 0.f);
            float4 r;
            r.x = h * (pos ? wp.x : wn.x);
            r.y = h * (pos ? wp.y : wn.y);
            r.z = h * (pos ? wp.z : wn.z);
            r.w = h * (pos ? wp.w : wn.w);
            __stcs(o + q, r);
        }
    }
}

extern "C" void kernel_launch(void* const* d_in, const int* in_sizes, int n_in,
                              void* d_out, int out_size) {
    const float* X = (const float*)d_in[0];   // [B, V, T]
    const float* A = (const float*)d_in[1];   // [T, V, V]
    const float* W = (const float*)d_in[2];   // [F, 1]
    float* out = (float*)d_out;               // [B, T, V*F]

    dim3 gprep(Tt, 2);
    adj_prep<<<gprep, 256>>>(A);

    // Fused with Programmatic Stream Serialization: pre-sync phase (X gather
    // + W preselect) overlaps adj_prep; griddepsync gates the g_adjT reads.
    cudaLaunchConfig_t cfg = {};
    cfg.gridDim  = dim3(Tt, Bb / 8);
    cfg.blockDim = dim3(256);
    cfg.dynamicSmemBytes = 0;
    cfg.stream = 0;
    cudaLaunchAttribute attr[1];
    attr[0].id = cudaLaunchAttributeProgrammaticStreamSerialization;
    attr[0].val.programmaticStreamSerializationAllowed = 1;
    cfg.attrs = attr;
    cfg.numAttrs = 1;
    cudaLaunchKernelEx(&cfg, fused_kernel, X, W, (float*)d_out);
}